// round 14
// baseline (speedup 1.0000x reference)
#include <cuda_runtime.h>
#include <cuda_bf16.h>
#include <cuda_fp16.h>
#include <math.h>

#define NUSER 50000
#define NITEM 100000
#define NNODE 150000
#define DD    64
#define NNZV  2400000
#define BB    1024
#define NSLOT 3072
#define SCAN_TILE 1024
#define NTILES ((NNODE + SCAN_TILE - 1) / SCAN_TILE)   // 147
#define CSR_BLKS NTILES                                 // 147 (<=148 SMs: co-resident)
#define CSR_THREADS (CSR_BLKS * 256)

typedef unsigned long long ull;

// ---------------- device scratch --------------------------------------------------
__device__ float4  g_E4[NNODE * 16];     // E0 users / E2 fp32 (38.4MB)
__device__ float4  g_Eb[NNODE * 16];     // E1 fp32 (38.4MB)
__device__ __half2 g_Eha[NNODE * 32];    // E0 fp16 -> later E2 fp16 (19.2MB)
__device__ __half2 g_Ehb[NNODE * 32];    // E1 fp16 (19.2MB)
__device__ int     g_slot[NSLOT];
__device__ unsigned char g_flag3[NNODE];
__device__ unsigned char g_flag2[NNODE];
__device__ int  g_list2[NNODE];
__device__ int  g_n2;
__device__ int  g_cnt[NNODE];
__device__ int  g_rp[NNODE + 1];
__device__ int  g_pos[NNODE];
__device__ int  g_tflag[NTILES];
__device__ int  g_bar[2];
__device__ int2 g_cv[NNZV];              // (col, val bits) row-sorted (19.2MB)

// ---------------- f32x2 packed-math helpers ---------------------------------------
__device__ __forceinline__ ull pack2(float x, float y) {
    ull r; asm("mov.b64 %0, {%1, %2};" : "=l"(r) : "f"(x), "f"(y)); return r;
}
__device__ __forceinline__ void unpack2(ull v, float &x, float &y) {
    asm("mov.b64 {%0, %1}, %2;" : "=f"(x), "=f"(y) : "l"(v));
}
__device__ __forceinline__ ull ffma2(ull a, ull b, ull c) {
    ull d; asm("fma.rn.f32x2 %0, %1, %2, %3;" : "=l"(d) : "l"(a), "l"(b), "l"(c)); return d;
}

// E0 fp32 row: users in g_E4, items straight from input
__device__ __forceinline__ const float2 *e0row(int c, const float2 *__restrict__ item2) {
    return (c < NUSER) ? ((const float2 *)g_E4) + (size_t)c * 32
                       : item2 + (size_t)(c - NUSER) * 32;
}

// ================= launch 0: user copy + item fp16 + zero aux =====================
#define COPYU_BLKS 3125            // NUSER*16/256
#define ITEM_BLKS  6250            // NITEM*16/256
#define ZERO_BLKS  586
#define INIT_BLKS (COPYU_BLKS + ITEM_BLKS + ZERO_BLKS)
__global__ void k_init(const float4 *__restrict__ ue, const float4 *__restrict__ ie) {
    int bid = blockIdx.x, tid = threadIdx.x;
    if (bid < COPYU_BLKS) {
        int i = bid * 256 + tid;                  // < NUSER*16 exactly
        float4 v = ue[i];
        g_E4[i] = v;
        g_Eha[2 * i]     = __floats2half2_rn(v.x, v.y);
        g_Eha[2 * i + 1] = __floats2half2_rn(v.z, v.w);
        return;
    }
    bid -= COPYU_BLKS;
    if (bid < ITEM_BLKS) {
        int i = bid * 256 + tid;                  // < NITEM*16 exactly
        float4 v = ie[i];
        int o = NUSER * 16 + i;
        g_Eha[2 * o]     = __floats2half2_rn(v.x, v.y);
        g_Eha[2 * o + 1] = __floats2half2_rn(v.z, v.w);
        return;
    }
    bid -= ITEM_BLKS;
    int i = bid * 256 + tid;
    if (i < NNODE) { g_cnt[i] = 0; g_flag3[i] = 0; g_flag2[i] = 0; }
    if (i < NTILES) g_tflag[i] = 0;
    if (i < 2) g_bar[i] = 0;
    if (i == 0) g_n2 = 0;
}

// ================= launch 1: MLP+update (last wins) + slots/flags =================
__global__ void k_prep(const int *__restrict__ uidx, const float *__restrict__ uemb,
                       const float *__restrict__ ratio,
                       const int *__restrict__ pi, const int *__restrict__ ni,
                       const float *__restrict__ l1w, const float *__restrict__ l1b,
                       const float *__restrict__ l2w, const float *__restrict__ l2b,
                       const float *__restrict__ feat) {
    int bid = blockIdx.x, tid = threadIdx.x;
    if (bid < 4) {
        int b = bid * 256 + tid;
        if (b >= BB) return;
        int u = uidx[b];
        for (int b2 = b + 1; b2 < BB; b2++)
            if (uidx[b2] == u) return;            // later duplicate wins
        float f0 = feat[b * 4 + 0], f1 = feat[b * 4 + 1];
        float f2 = feat[b * 4 + 2], f3 = feat[b * 4 + 3];
        float h[32];
#pragma unroll
        for (int j = 0; j < 32; j++)
            h[j] = l1b[j] + f0 * l1w[j] + f1 * l1w[32 + j] + f2 * l1w[64 + j] + f3 * l1w[96 + j];
        float r = *ratio;
        float e[64];
#pragma unroll 4
        for (int o = 0; o < 64; o++) {
            float a = l2b[o];
#pragma unroll
            for (int j = 0; j < 32; j++) a += h[j] * l2w[j * 64 + o];
            e[o] = uemb[u * 64 + o] * (1.0f - r) + a * r;
        }
        float4 *er = g_E4 + (size_t)u * 16;
        __half2 *eh = g_Eha + (size_t)u * 32;
#pragma unroll
        for (int j = 0; j < 16; j++) {
            er[j] = make_float4(e[4 * j], e[4 * j + 1], e[4 * j + 2], e[4 * j + 3]);
            eh[2 * j]     = __floats2half2_rn(e[4 * j], e[4 * j + 1]);
            eh[2 * j + 1] = __floats2half2_rn(e[4 * j + 2], e[4 * j + 3]);
        }
        return;
    }
    int s = (bid - 4) * 256 + tid;
    if (s >= NSLOT) return;
    int node;
    if (s < 1024)       node = uidx[s];
    else if (s < 2048)  node = NUSER + pi[s - 1024];
    else                node = NUSER + ni[s - 2048];
    g_slot[s] = node;
    g_flag3[node] = 1;
    g_flag2[node] = 1;
}

// ---------------- grid-wide barrier (all CSR_BLKS co-resident) --------------------
__device__ __forceinline__ void grid_barrier(int idx) {
    __syncthreads();
    if (threadIdx.x == 0) {
        __threadfence();
        atomicAdd(&g_bar[idx], 1);
        while (atomicAdd(&g_bar[idx], 0) < CSR_BLKS) {}
    }
    __syncthreads();
}

// ================= launch 2: persistent CSR build (hist->scan->scatter) ===========
__global__ __launch_bounds__(256) void k_csr(const int *__restrict__ row,
                                             const int *__restrict__ col,
                                             const float *__restrict__ val,
                                             float *__restrict__ out,
                                             const float2 *__restrict__ item2) {
    int tid = threadIdx.x, blk = blockIdx.x;
    int id = blk * 256 + tid;

    // --- phase A: histogram + flag2 propagate + gather0 (E0 -> out[:,0:64]) ---
    for (int i = id; i < NNZV; i += CSR_THREADS) {
        int r = __ldg(row + i);
        atomicAdd(&g_cnt[r], 1);
        if (g_flag3[r]) g_flag2[__ldg(col + i)] = 1;
    }
    for (int t = id; t < NSLOT * 32; t += CSR_THREADS) {
        int slot = t >> 5, lane = t & 31;
        int node = g_slot[slot];
        float2 v = __ldg(e0row(node, item2) + lane);
        ((float2 *)(out + (size_t)slot * 256))[lane] = v;
    }
    grid_barrier(0);

    // --- phase B: tile scan (lookback) + rp/pos + list2 ---
    {
        __shared__ int wsum[8], rs[8], sS;
        int lane = tid & 31, wid = tid >> 5;
        int idx = blk * SCAN_TILE + tid * 4;
        int v0 = (idx + 0 < NNODE) ? g_cnt[idx + 0] : 0;
        int v1 = (idx + 1 < NNODE) ? g_cnt[idx + 1] : 0;
        int v2 = (idx + 2 < NNODE) ? g_cnt[idx + 2] : 0;
        int v3 = (idx + 3 < NNODE) ? g_cnt[idx + 3] : 0;
        int s = v0 + v1 + v2 + v3;
        int x = s;
#pragma unroll
        for (int o = 1; o < 32; o <<= 1) {
            int y = __shfl_up_sync(0xffffffffu, x, o);
            if (lane >= o) x += y;
        }
        if (lane == 31) wsum[wid] = x;
        __syncthreads();
        if (wid == 0) {
            int y = (lane < 8) ? wsum[lane] : 0;
#pragma unroll
            for (int o = 1; o < 8; o <<= 1) {
                int z = __shfl_up_sync(0xffffffffu, y, o);
                if (lane >= o) y += z;
            }
            if (lane < 8) wsum[lane] = y;
        }
        __syncthreads();
        int run = x - s + (wid > 0 ? wsum[wid - 1] : 0);
        if (tid == 0) atomicExch(&g_tflag[blk], wsum[7] + 1);
        int v = 0;
        if (tid < blk) {
            int t;
            while ((t = atomicAdd(&g_tflag[tid], 0)) == 0) {}
            v = t - 1;
        }
#pragma unroll
        for (int o = 16; o > 0; o >>= 1) v += __shfl_xor_sync(0xffffffffu, v, o);
        if (lane == 0) rs[wid] = v;
        __syncthreads();
        if (tid == 0) {
            int S = 0;
#pragma unroll
            for (int i = 0; i < 8; i++) S += rs[i];
            sS = S;
        }
        __syncthreads();
        int S = sS;
        int r0 = run + S, r1 = r0 + v0, r2 = r1 + v1, r3 = r2 + v2;
        if (idx + 0 < NNODE) { g_rp[idx + 0] = r0; g_pos[idx + 0] = r0;
            if (g_flag2[idx + 0]) g_list2[atomicAdd(&g_n2, 1)] = idx + 0; }
        if (idx + 1 < NNODE) { g_rp[idx + 1] = r1; g_pos[idx + 1] = r1;
            if (g_flag2[idx + 1]) g_list2[atomicAdd(&g_n2, 1)] = idx + 1; }
        if (idx + 2 < NNODE) { g_rp[idx + 2] = r2; g_pos[idx + 2] = r2;
            if (g_flag2[idx + 2]) g_list2[atomicAdd(&g_n2, 1)] = idx + 2; }
        if (idx + 3 < NNODE) { g_rp[idx + 3] = r3; g_pos[idx + 3] = r3;
            if (g_flag2[idx + 3]) g_list2[atomicAdd(&g_n2, 1)] = idx + 3; }
        if (blk == 0 && tid == 0) g_rp[NNODE] = NNZV;
    }
    grid_barrier(1);

    // --- phase C: scatter (col,val) row-sorted ---
    for (int i = id; i < NNZV; i += CSR_THREADS) {
        int p = atomicAdd(&g_pos[row[i]], 1);
        g_cv[p] = make_int2(col[i], __float_as_int(val[i]));
    }
}

// ================= CSR SpMM row body: fp16 gather, fp32 accumulate ================
__device__ __forceinline__ float2 spmm_row_val(const __half2 *__restrict__ Eh,
                                               int r, int lane) {
    int j = __ldg(&g_rp[r]), end = __ldg(&g_rp[r + 1]);
    float ax = 0.f, ay = 0.f;
#define LDE(c) __half22float2(__ldg(Eh + (size_t)(c) * 32 + lane))
    if ((j & 1) && j < end) {
        int2 c = __ldg(g_cv + j);
        float2 e = LDE(c.x);
        float v = __int_as_float(c.y);
        ax += v * e.x; ay += v * e.y;
        j++;
    }
    for (; j + 8 <= end; j += 8) {
        int4 q0 = __ldg((const int4 *)(g_cv + j));
        int4 q1 = __ldg((const int4 *)(g_cv + j + 2));
        int4 q2 = __ldg((const int4 *)(g_cv + j + 4));
        int4 q3 = __ldg((const int4 *)(g_cv + j + 6));
        float2 e0 = LDE(q0.x), e1 = LDE(q0.z);
        float2 e2 = LDE(q1.x), e3 = LDE(q1.z);
        float2 e4 = LDE(q2.x), e5 = LDE(q2.z);
        float2 e6 = LDE(q3.x), e7 = LDE(q3.z);
        ax += __int_as_float(q0.y) * e0.x; ay += __int_as_float(q0.y) * e0.y;
        ax += __int_as_float(q0.w) * e1.x; ay += __int_as_float(q0.w) * e1.y;
        ax += __int_as_float(q1.y) * e2.x; ay += __int_as_float(q1.y) * e2.y;
        ax += __int_as_float(q1.w) * e3.x; ay += __int_as_float(q1.w) * e3.y;
        ax += __int_as_float(q2.y) * e4.x; ay += __int_as_float(q2.y) * e4.y;
        ax += __int_as_float(q2.w) * e5.x; ay += __int_as_float(q2.w) * e5.y;
        ax += __int_as_float(q3.y) * e6.x; ay += __int_as_float(q3.y) * e6.y;
        ax += __int_as_float(q3.w) * e7.x; ay += __int_as_float(q3.w) * e7.y;
    }
    for (; j < end; j++) {
        int2 c = __ldg(g_cv + j);
        float2 e = LDE(c.x);
        float v = __int_as_float(c.y);
        ax += v * e.x; ay += v * e.y;
    }
#undef LDE
    return make_float2(ax, ay);
}

// ================= fused layer: SpMM -> smem -> GEMM + epilogue ===================
// MODE 0: all rows, E0 in (g_Eha fp16 / e0row fp32), E1 out (g_Eb + g_Ehb)
// MODE 1: list2 rows, E1 in (g_Ehb / g_Eb), E2 out (g_E4 + g_Eha); appended gather1
// MODE 2: slot rows, E2 in (g_Eha / g_E4), out cols [192:256) + norm; appended gather2
#define LSMEM_BYTES (4128 * 8 + 256 * 65 * 4)   // 33024 + 66560 = 99584
template <int MODE>
__global__ __launch_bounds__(256, 2) void k_layer(const float *__restrict__ w1,
                                                  const float *__restrict__ b1,
                                                  const float *__restrict__ w2,
                                                  const float *__restrict__ b2,
                                                  const float2 *__restrict__ item2,
                                                  int spmm_blks,
                                                  float *__restrict__ out) {
    // appended gather blocks (normalized copy of previous layer's E into out)
    if (MODE != 0 && (int)blockIdx.x >= spmm_blks) {
        int t = ((int)blockIdx.x - spmm_blks) * 256 + threadIdx.x;
        int slot = t >> 5, lane = t & 31;
        if (slot >= NSLOT) return;
        int node = g_slot[slot];
        const float2 *src = (MODE == 1) ? (const float2 *)g_Eb : (const float2 *)g_E4;
        float2 v = src[(size_t)node * 32 + lane];
        float s = v.x * v.x + v.y * v.y;
#pragma unroll
        for (int o = 16; o > 0; o >>= 1) s += __shfl_xor_sync(0xffffffffu, s, o);
        float sc = 1.0f / fmaxf(sqrtf(s), 1e-12f);
        v.x *= sc; v.y *= sc;
        ((float2 *)(out + (size_t)slot * 256 + (MODE == 1 ? 64 : 128)))[lane] = v;
        return;
    }

    extern __shared__ ull smem_u[];
    ull *sW1 = smem_u;               // 2048
    ull *sW2 = smem_u + 2048;        // 2048
    ull *sB  = smem_u + 4096;        // 32
    float *sLE = (float *)(smem_u + 4128);   // 256 rows * stride 65

    for (int i = threadIdx.x; i < 2048; i += 256) {
        sW1[i] = ((const ull *)w1)[i];
        sW2[i] = ((const ull *)w2)[i];
    }
    if (threadIdx.x < 32) {
        int t = threadIdx.x;
        sB[t] = pack2(b1[2 * t] + b2[2 * t], b1[2 * t + 1] + b2[2 * t + 1]);
    }

    int wid = threadIdx.x >> 5, lane = threadIdx.x & 31;
    int nrows = (MODE == 0) ? NNODE : ((MODE == 1) ? g_n2 : NSLOT);
    const __half2 *Eh = (MODE == 1) ? g_Ehb : g_Eha;

    for (int chunk = blockIdx.x; chunk * 256 < nrows; chunk += spmm_blks) {
        int base = chunk * 256;

        // ---- SpMM phase: warp computes 32 rows, stores to padded smem ----
        for (int rr = 0; rr < 32; rr++) {
            int g = base + wid * 32 + rr;
            if (g < nrows) {
                int r = (MODE == 0) ? g : ((MODE == 1) ? g_list2[g] : g_slot[g]);
                float2 a = spmm_row_val(Eh, r, lane);
                int l = wid * 32 + rr;
                sLE[l * 65 + 2 * lane]     = a.x;
                sLE[l * 65 + 2 * lane + 1] = a.y;
            }
        }
        __syncthreads();

        // ---- GEMM phase: thread per row ----
        int g = base + threadIdx.x;
        if (g < nrows) {
            int r = (MODE == 0) ? g : ((MODE == 1) ? g_list2[g] : g_slot[g]);
            const float *le = sLE + threadIdx.x * 65;
            const float4 *ep4 =
                (MODE == 0) ? (const float4 *)e0row(r, item2)
                            : (MODE == 1) ? (const float4 *)(g_Eb + (size_t)r * 16)
                                          : (const float4 *)(g_E4 + (size_t)r * 16);
            ull acc[32];
#pragma unroll
            for (int j = 0; j < 32; j++) acc[j] = sB[j];

#pragma unroll
            for (int ph = 0; ph < 4; ph++) {
                float ee[16];
#pragma unroll
                for (int q = 0; q < 4; q++) {
                    float4 b = __ldg(ep4 + ph * 4 + q);
                    ee[4 * q] = b.x; ee[4 * q + 1] = b.y;
                    ee[4 * q + 2] = b.z; ee[4 * q + 3] = b.w;
                }
#pragma unroll
                for (int kk = 0; kk < 16; kk++) {
                    int k = ph * 16 + kk;
                    float lev = le[k];
                    float a = lev + ee[kk], m = lev * ee[kk];
                    ull a2 = pack2(a, a), m2 = pack2(m, m);
                    const ulonglong2 *wA = (const ulonglong2 *)(sW1 + k * 32);
                    const ulonglong2 *wB = (const ulonglong2 *)(sW2 + k * 32);
#pragma unroll
                    for (int j = 0; j < 16; j++) {
                        ulonglong2 pa = wA[j];
                        ulonglong2 pb = wB[j];
                        acc[2 * j]     = ffma2(a2, pa.x, acc[2 * j]);
                        acc[2 * j + 1] = ffma2(a2, pa.y, acc[2 * j + 1]);
                        acc[2 * j]     = ffma2(m2, pb.x, acc[2 * j]);
                        acc[2 * j + 1] = ffma2(m2, pb.y, acc[2 * j + 1]);
                    }
                }
            }

            if (MODE == 2) {
                float ss = 0.f;
#pragma unroll
                for (int j = 0; j < 32; j++) {
                    float x, y;
                    unpack2(acc[j], x, y);
                    x = (x >= 0.f) ? x : 0.2f * x;
                    y = (y >= 0.f) ? y : 0.2f * y;
                    acc[j] = pack2(x, y);
                    ss += x * x + y * y;
                }
                float sc = 1.0f / fmaxf(sqrtf(ss), 1e-12f);
                float *op = out + (size_t)g * 256 + 192;
#pragma unroll
                for (int j = 0; j < 16; j++) {
                    float x0, x1, x2, x3;
                    unpack2(acc[2 * j], x0, x1);
                    unpack2(acc[2 * j + 1], x2, x3);
                    ((float4 *)op)[j] = make_float4(x0 * sc, x1 * sc, x2 * sc, x3 * sc);
                }
            } else {
                float4 *of = (MODE == 0) ? (g_Eb + (size_t)r * 16) : (g_E4 + (size_t)r * 16);
                __half2 *oh = (MODE == 0) ? (g_Ehb + (size_t)r * 32) : (g_Eha + (size_t)r * 32);
#pragma unroll
                for (int j = 0; j < 16; j++) {
                    float x0, x1, x2, x3;
                    unpack2(acc[2 * j], x0, x1);
                    unpack2(acc[2 * j + 1], x2, x3);
                    x0 = (x0 >= 0.f) ? x0 : 0.2f * x0;
                    x1 = (x1 >= 0.f) ? x1 : 0.2f * x1;
                    x2 = (x2 >= 0.f) ? x2 : 0.2f * x2;
                    x3 = (x3 >= 0.f) ? x3 : 0.2f * x3;
                    of[j] = make_float4(x0, x1, x2, x3);
                    oh[2 * j]     = __floats2half2_rn(x0, x1);
                    oh[2 * j + 1] = __floats2half2_rn(x2, x3);
                }
            }
        }
        __syncthreads();
    }
}

// =================================================================================
extern "C" void kernel_launch(void* const* d_in, const int* in_sizes, int n_in,
                              void* d_out, int out_size) {
    const float *user_emb, *item_emb, *user_feat, *lin1_w, *lin1_b, *lin2_w, *lin2_b;
    const float *w1, *b1, *w2, *b2, *lap_val, *mlp_ratio;
    const int *lap_row, *lap_col, *user_idx, *pos_idx, *neg_idx;

    if (in_sizes[2] == 4096) {
        user_emb  = (const float *)d_in[0];
        item_emb  = (const float *)d_in[1];
        user_feat = (const float *)d_in[2];
        lin1_w    = (const float *)d_in[3];
        lin1_b    = (const float *)d_in[4];
        lin2_w    = (const float *)d_in[5];
        lin2_b    = (const float *)d_in[6];
        w1        = (const float *)d_in[7];
        b1        = (const float *)d_in[8];
        w2        = (const float *)d_in[9];
        b2        = (const float *)d_in[10];
        lap_val   = (const float *)d_in[11];
        mlp_ratio = (const float *)d_in[12];
        lap_row   = (const int *)d_in[13];
        lap_col   = (const int *)d_in[14];
        user_idx  = (const int *)d_in[15];
        pos_idx   = (const int *)d_in[16];
        neg_idx   = (const int *)d_in[17];
    } else {
        user_emb  = (const float *)d_in[0];
        item_emb  = (const float *)d_in[1];
        lin1_w    = (const float *)d_in[2];
        lin1_b    = (const float *)d_in[3];
        lin2_w    = (const float *)d_in[4];
        lin2_b    = (const float *)d_in[5];
        w1        = (const float *)d_in[6];
        b1        = (const float *)d_in[7];
        w2        = (const float *)d_in[8];
        b2        = (const float *)d_in[9];
        lap_row   = (const int *)d_in[10];
        lap_col   = (const int *)d_in[11];
        lap_val   = (const float *)d_in[12];
        user_idx  = (const int *)d_in[13];
        user_feat = (const float *)d_in[14];
        pos_idx   = (const int *)d_in[15];
        neg_idx   = (const int *)d_in[16];
        mlp_ratio = (const float *)d_in[17];
    }

    float *out = (float *)d_out;
    const float2 *item2 = (const float2 *)item_emb;

    // raise dynamic smem limit (idempotent; first call happens outside capture)
    cudaFuncSetAttribute(k_layer<0>, cudaFuncAttributeMaxDynamicSharedMemorySize, LSMEM_BYTES);
    cudaFuncSetAttribute(k_layer<1>, cudaFuncAttributeMaxDynamicSharedMemorySize, LSMEM_BYTES);
    cudaFuncSetAttribute(k_layer<2>, cudaFuncAttributeMaxDynamicSharedMemorySize, LSMEM_BYTES);

    const int T = 256;
    const int gGath = (NSLOT * 32) / T;              // 384
    const int gL1   = (NNODE + 255) / 256;           // 587
    const int gL2S  = 200;                           // layer-2 spmm/gemm blocks (strided)
    const int gL3S  = NSLOT / 256;                   // 12

    // 0: user E0 copy(+fp16) + item fp16 + zero aux
    k_init<<<INIT_BLKS, T>>>((const float4 *)user_emb, (const float4 *)item_emb);
    // 1: fused MLP+scatter-update(+fp16) + slots/flags
    k_prep<<<16, T>>>(user_idx, user_emb, mlp_ratio, pos_idx, neg_idx,
                      lin1_w, lin1_b, lin2_w, lin2_b, user_feat);
    // 2: persistent CSR build (hist+flag2+gather0 -> scan+list2 -> scatter)
    k_csr<<<CSR_BLKS, T>>>(lap_row, lap_col, lap_val, out, item2);
    // 3: layer 1 fused (full)  <-- profiled slot
    k_layer<0><<<gL1, T, LSMEM_BYTES>>>(w1, b1, w2, b2, item2, gL1, nullptr);
    // 4: layer 2 fused (list2, strided) || gather1 -> out[:,64:128]
    k_layer<1><<<gL2S + gGath, T, LSMEM_BYTES>>>(w1 + 4096, b1 + 64, w2 + 4096, b2 + 64,
                                                 item2, gL2S, out);
    // 5: layer 3 fused (slots, norm -> out[:,192:256]) || gather2 -> out[:,128:192]
    k_layer<2><<<gL3S + gGath, T, LSMEM_BYTES>>>(w1 + 2 * 4096, b1 + 2 * 64,
                                                 w2 + 2 * 4096, b2 + 2 * 64,
                                                 item2, gL3S, out);
}

// round 15
// speedup vs baseline: 2.0097x; 2.0097x over previous
#include <cuda_runtime.h>
#include <cuda_bf16.h>
#include <cuda_fp16.h>
#include <math.h>

#define NUSER 50000
#define NITEM 100000
#define NNODE 150000
#define DD    64
#define NNZV  2400000
#define BB    1024
#define NSLOT 3072
#define SCAN_TILE 1024
#define NTILES ((NNODE + SCAN_TILE - 1) / SCAN_TILE)   // 147
#define CSR_BLKS NTILES                                 // 147 (<=148 SMs: co-resident)
#define CSR_THREADS (CSR_BLKS * 256)
#define SP2_WARPS 37888                                 // 4736 blocks * 8 warps

typedef unsigned long long ull;

// ---------------- device scratch --------------------------------------------------
__device__ float4  g_E4[NNODE * 16];     // fp32 node embeddings, in-place per layer
__device__ __half2 g_Eh[NNODE * 32];     // fp16 mirror for SpMM gather (19.2MB)
__device__ float4  g_LE4[NNODE * 16];    // SpMM result (38.4MB)
__device__ int     g_slot[NSLOT];
__device__ unsigned char g_flag3[NNODE];
__device__ unsigned char g_flag2[NNODE];
__device__ int  g_list2[NNODE];
__device__ int  g_n2;
__device__ int  g_cnt[NNODE];
__device__ int  g_rp[NNODE + 1];
__device__ int  g_pos[NNODE];
__device__ int  g_tflag[NTILES];
__device__ int  g_bar[2];
__device__ int2 g_cv[NNZV];              // (col, val bits) row-sorted (19.2MB)

// ---------------- f32x2 packed-math helpers ---------------------------------------
__device__ __forceinline__ ull pack2(float x, float y) {
    ull r; asm("mov.b64 %0, {%1, %2};" : "=l"(r) : "f"(x), "f"(y)); return r;
}
__device__ __forceinline__ void unpack2(ull v, float &x, float &y) {
    asm("mov.b64 {%0, %1}, %2;" : "=f"(x), "=f"(y) : "l"(v));
}
__device__ __forceinline__ ull ffma2(ull a, ull b, ull c) {
    ull d; asm("fma.rn.f32x2 %0, %1, %2, %3;" : "=l"(d) : "l"(a), "l"(b), "l"(c)); return d;
}

// E0 fp32 row: users in g_E4, items straight from input
__device__ __forceinline__ const float2 *e0row(int c, const float2 *__restrict__ item2) {
    return (c < NUSER) ? ((const float2 *)g_E4) + (size_t)c * 32
                       : item2 + (size_t)(c - NUSER) * 32;
}

// ================= launch 0: user copy + item fp16 + zero aux =====================
#define COPYU_BLKS 3125            // NUSER*16/256
#define ITEM_BLKS  6250            // NITEM*16/256
#define ZERO_BLKS  586
#define INIT_BLKS (COPYU_BLKS + ITEM_BLKS + ZERO_BLKS)
__global__ void k_init(const float4 *__restrict__ ue, const float4 *__restrict__ ie) {
    int bid = blockIdx.x, tid = threadIdx.x;
    if (bid < COPYU_BLKS) {
        int i = bid * 256 + tid;                  // < NUSER*16 exactly
        float4 v = ue[i];
        g_E4[i] = v;
        g_Eh[2 * i]     = __floats2half2_rn(v.x, v.y);
        g_Eh[2 * i + 1] = __floats2half2_rn(v.z, v.w);
        return;
    }
    bid -= COPYU_BLKS;
    if (bid < ITEM_BLKS) {
        int i = bid * 256 + tid;                  // < NITEM*16 exactly
        float4 v = ie[i];
        int o = NUSER * 16 + i;
        g_Eh[2 * o]     = __floats2half2_rn(v.x, v.y);
        g_Eh[2 * o + 1] = __floats2half2_rn(v.z, v.w);
        return;
    }
    bid -= ITEM_BLKS;
    int i = bid * 256 + tid;
    if (i < NNODE) { g_cnt[i] = 0; g_flag3[i] = 0; g_flag2[i] = 0; }
    if (i < NTILES) g_tflag[i] = 0;
    if (i < 2) g_bar[i] = 0;
    if (i == 0) g_n2 = 0;
}

// ================= launch 1: MLP+update (last wins) + slots/flags =================
__global__ void k_prep(const int *__restrict__ uidx, const float *__restrict__ uemb,
                       const float *__restrict__ ratio,
                       const int *__restrict__ pi, const int *__restrict__ ni,
                       const float *__restrict__ l1w, const float *__restrict__ l1b,
                       const float *__restrict__ l2w, const float *__restrict__ l2b,
                       const float *__restrict__ feat) {
    int bid = blockIdx.x, tid = threadIdx.x;
    if (bid < 4) {
        int b = bid * 256 + tid;
        if (b >= BB) return;
        int u = uidx[b];
        for (int b2 = b + 1; b2 < BB; b2++)
            if (uidx[b2] == u) return;            // later duplicate wins
        float f0 = feat[b * 4 + 0], f1 = feat[b * 4 + 1];
        float f2 = feat[b * 4 + 2], f3 = feat[b * 4 + 3];
        float h[32];
#pragma unroll
        for (int j = 0; j < 32; j++)
            h[j] = l1b[j] + f0 * l1w[j] + f1 * l1w[32 + j] + f2 * l1w[64 + j] + f3 * l1w[96 + j];
        float r = *ratio;
        float e[64];
#pragma unroll 4
        for (int o = 0; o < 64; o++) {
            float a = l2b[o];
#pragma unroll
            for (int j = 0; j < 32; j++) a += h[j] * l2w[j * 64 + o];
            e[o] = uemb[u * 64 + o] * (1.0f - r) + a * r;
        }
        float4 *er = g_E4 + (size_t)u * 16;
        __half2 *eh = g_Eh + (size_t)u * 32;
#pragma unroll
        for (int j = 0; j < 16; j++) {
            er[j] = make_float4(e[4 * j], e[4 * j + 1], e[4 * j + 2], e[4 * j + 3]);
            eh[2 * j]     = __floats2half2_rn(e[4 * j], e[4 * j + 1]);
            eh[2 * j + 1] = __floats2half2_rn(e[4 * j + 2], e[4 * j + 3]);
        }
        return;
    }
    int s = (bid - 4) * 256 + tid;
    if (s >= NSLOT) return;
    int node;
    if (s < 1024)       node = uidx[s];
    else if (s < 2048)  node = NUSER + pi[s - 1024];
    else                node = NUSER + ni[s - 2048];
    g_slot[s] = node;
    g_flag3[node] = 1;
    g_flag2[node] = 1;
}

// ---------------- grid-wide barrier (all CSR_BLKS co-resident) --------------------
__device__ __forceinline__ void grid_barrier(int idx) {
    __syncthreads();
    if (threadIdx.x == 0) {
        __threadfence();
        atomicAdd(&g_bar[idx], 1);
        while (atomicAdd(&g_bar[idx], 0) < CSR_BLKS) {}
    }
    __syncthreads();
}

// ================= launch 2: persistent CSR build (hist->scan->scatter) ===========
__global__ __launch_bounds__(256) void k_csr(const int *__restrict__ row,
                                             const int *__restrict__ col,
                                             const float *__restrict__ val,
                                             float *__restrict__ out,
                                             const float2 *__restrict__ item2) {
    int tid = threadIdx.x, blk = blockIdx.x;
    int id = blk * 256 + tid;

    // --- phase A: histogram + flag2 propagate + gather0 (E0 -> out[:,0:64]) ---
    for (int i = id; i < NNZV; i += CSR_THREADS) {
        int r = __ldg(row + i);
        atomicAdd(&g_cnt[r], 1);
        if (g_flag3[r]) g_flag2[__ldg(col + i)] = 1;
    }
    for (int t = id; t < NSLOT * 32; t += CSR_THREADS) {
        int slot = t >> 5, lane = t & 31;
        int node = g_slot[slot];
        float2 v = __ldg(e0row(node, item2) + lane);
        ((float2 *)(out + (size_t)slot * 256))[lane] = v;
    }
    grid_barrier(0);

    // --- phase B: tile scan (lookback) + rp/pos + list2 ---
    {
        __shared__ int wsum[8], rs[8], sS;
        int lane = tid & 31, wid = tid >> 5;
        int idx = blk * SCAN_TILE + tid * 4;
        int v0 = (idx + 0 < NNODE) ? g_cnt[idx + 0] : 0;
        int v1 = (idx + 1 < NNODE) ? g_cnt[idx + 1] : 0;
        int v2 = (idx + 2 < NNODE) ? g_cnt[idx + 2] : 0;
        int v3 = (idx + 3 < NNODE) ? g_cnt[idx + 3] : 0;
        int s = v0 + v1 + v2 + v3;
        int x = s;
#pragma unroll
        for (int o = 1; o < 32; o <<= 1) {
            int y = __shfl_up_sync(0xffffffffu, x, o);
            if (lane >= o) x += y;
        }
        if (lane == 31) wsum[wid] = x;
        __syncthreads();
        if (wid == 0) {
            int y = (lane < 8) ? wsum[lane] : 0;
#pragma unroll
            for (int o = 1; o < 8; o <<= 1) {
                int z = __shfl_up_sync(0xffffffffu, y, o);
                if (lane >= o) y += z;
            }
            if (lane < 8) wsum[lane] = y;
        }
        __syncthreads();
        int run = x - s + (wid > 0 ? wsum[wid - 1] : 0);
        if (tid == 0) atomicExch(&g_tflag[blk], wsum[7] + 1);
        int v = 0;
        if (tid < blk) {
            int t;
            while ((t = atomicAdd(&g_tflag[tid], 0)) == 0) {}
            v = t - 1;
        }
#pragma unroll
        for (int o = 16; o > 0; o >>= 1) v += __shfl_xor_sync(0xffffffffu, v, o);
        if (lane == 0) rs[wid] = v;
        __syncthreads();
        if (tid == 0) {
            int S = 0;
#pragma unroll
            for (int i = 0; i < 8; i++) S += rs[i];
            sS = S;
        }
        __syncthreads();
        int S = sS;
        int r0 = run + S, r1 = r0 + v0, r2 = r1 + v1, r3 = r2 + v2;
        if (idx + 0 < NNODE) { g_rp[idx + 0] = r0; g_pos[idx + 0] = r0;
            if (g_flag2[idx + 0]) g_list2[atomicAdd(&g_n2, 1)] = idx + 0; }
        if (idx + 1 < NNODE) { g_rp[idx + 1] = r1; g_pos[idx + 1] = r1;
            if (g_flag2[idx + 1]) g_list2[atomicAdd(&g_n2, 1)] = idx + 1; }
        if (idx + 2 < NNODE) { g_rp[idx + 2] = r2; g_pos[idx + 2] = r2;
            if (g_flag2[idx + 2]) g_list2[atomicAdd(&g_n2, 1)] = idx + 2; }
        if (idx + 3 < NNODE) { g_rp[idx + 3] = r3; g_pos[idx + 3] = r3;
            if (g_flag2[idx + 3]) g_list2[atomicAdd(&g_n2, 1)] = idx + 3; }
        if (blk == 0 && tid == 0) g_rp[NNODE] = NNZV;
    }
    grid_barrier(1);

    // --- phase C: scatter (col,val) row-sorted ---
    for (int i = id; i < NNZV; i += CSR_THREADS) {
        int p = atomicAdd(&g_pos[row[i]], 1);
        g_cv[p] = make_int2(col[i], __float_as_int(val[i]));
    }
}

// ================= CSR SpMM row body: fp16 gather, fp32 accumulate ================
__device__ __forceinline__ void spmm_row(int r, int lane) {
    int j = __ldg(&g_rp[r]), end = __ldg(&g_rp[r + 1]);
    float ax = 0.f, ay = 0.f;
#define LDE(c) __half22float2(__ldg(g_Eh + (size_t)(c) * 32 + lane))
    if ((j & 1) && j < end) {
        int2 c = __ldg(g_cv + j);
        float2 e = LDE(c.x);
        float v = __int_as_float(c.y);
        ax += v * e.x; ay += v * e.y;
        j++;
    }
    for (; j + 8 <= end; j += 8) {
        int4 q0 = __ldg((const int4 *)(g_cv + j));
        int4 q1 = __ldg((const int4 *)(g_cv + j + 2));
        int4 q2 = __ldg((const int4 *)(g_cv + j + 4));
        int4 q3 = __ldg((const int4 *)(g_cv + j + 6));
        float2 e0 = LDE(q0.x), e1 = LDE(q0.z);
        float2 e2 = LDE(q1.x), e3 = LDE(q1.z);
        float2 e4 = LDE(q2.x), e5 = LDE(q2.z);
        float2 e6 = LDE(q3.x), e7 = LDE(q3.z);
        ax += __int_as_float(q0.y) * e0.x; ay += __int_as_float(q0.y) * e0.y;
        ax += __int_as_float(q0.w) * e1.x; ay += __int_as_float(q0.w) * e1.y;
        ax += __int_as_float(q1.y) * e2.x; ay += __int_as_float(q1.y) * e2.y;
        ax += __int_as_float(q1.w) * e3.x; ay += __int_as_float(q1.w) * e3.y;
        ax += __int_as_float(q2.y) * e4.x; ay += __int_as_float(q2.y) * e4.y;
        ax += __int_as_float(q2.w) * e5.x; ay += __int_as_float(q2.w) * e5.y;
        ax += __int_as_float(q3.y) * e6.x; ay += __int_as_float(q3.y) * e6.y;
        ax += __int_as_float(q3.w) * e7.x; ay += __int_as_float(q3.w) * e7.y;
    }
    for (; j < end; j++) {
        int2 c = __ldg(g_cv + j);
        float2 e = LDE(c.x);
        float v = __int_as_float(c.y);
        ax += v * e.x; ay += v * e.y;
    }
#undef LDE
    ((float2 *)g_LE4)[(size_t)r * 32 + lane] = make_float2(ax, ay);
}

// ---------------- gather body (fp32 E, normalized) --------------------------------
__device__ __forceinline__ void gather_body(int t, float *__restrict__ out, int col_off) {
    int slot = t >> 5, lane = t & 31;
    if (slot >= NSLOT) return;
    int node = g_slot[slot];
    float2 v = ((const float2 *)g_E4)[(size_t)node * 32 + lane];
    float s = v.x * v.x + v.y * v.y;
#pragma unroll
    for (int o = 16; o > 0; o >>= 1) s += __shfl_xor_sync(0xffffffffu, s, o);
    float sc = 1.0f / fmaxf(sqrtf(s), 1e-12f);
    v.x *= sc; v.y *= sc;
    ((float2 *)(out + (size_t)slot * 256 + col_off))[lane] = v;
}

// MODE 0 = all rows (flat), 1 = list2 rows (grid-strided), 2 = slot rows (flat)
template <int MODE>
__global__ void k_spmm(int spmm_blks, float *__restrict__ out, int col_off) {
    int bid = blockIdx.x;
    if (MODE != 0 && bid >= spmm_blks) {
        gather_body((bid - spmm_blks) * 256 + threadIdx.x, out, col_off);
        return;
    }
    int lane = threadIdx.x & 31;
    int w = (bid * blockDim.x + threadIdx.x) >> 5;
    if (MODE == 0) {
        if (w < NNODE) spmm_row(w, lane);
    } else if (MODE == 1) {
        int n2 = g_n2;
        for (; w < n2; w += SP2_WARPS) spmm_row(g_list2[w], lane);
    } else {
        if (w < NSLOT) spmm_row(g_slot[w], lane);
    }
}

// ================= GEMM + leaky_relu, E in place, fp16 mirror epilogue ============
// MODE 0 = all rows (layer 1, E0 via select), 1 = list2 rows grid-strided (layer 2)
template <int MODE>
__global__ __launch_bounds__(128) void k_gemm(const float *__restrict__ w1,
                                              const float *__restrict__ b1,
                                              const float *__restrict__ w2,
                                              const float *__restrict__ b2,
                                              const float2 *__restrict__ item2) {
    __shared__ ull sW1[2048], sW2[2048], sB[32];
    const ull *w1p = (const ull *)w1;
    const ull *w2p = (const ull *)w2;
    for (int i = threadIdx.x; i < 2048; i += 128) { sW1[i] = w1p[i]; sW2[i] = w2p[i]; }
    if (threadIdx.x < 32) {
        int t = threadIdx.x;
        sB[t] = pack2(b1[2 * t] + b2[2 * t], b1[2 * t + 1] + b2[2 * t + 1]);
    }
    __syncthreads();

    int idx = blockIdx.x * 128 + threadIdx.x;
    int nrows = (MODE == 0) ? NNODE : g_n2;
    int stride = gridDim.x * 128;

    for (; idx < nrows; idx += stride) {
        int rrow = (MODE == 0) ? idx : g_list2[idx];

        ull acc[32];
#pragma unroll
        for (int j = 0; j < 32; j++) acc[j] = sB[j];

        const float4 *lep4 = (const float4 *)(g_LE4 + (size_t)rrow * 16);
        const float4 *ep4  = (MODE == 0) ? (const float4 *)e0row(rrow, item2)
                                         : (const float4 *)(g_E4 + (size_t)rrow * 16);

#pragma unroll
        for (int ph = 0; ph < 4; ph++) {
            float le[16], ee[16];
#pragma unroll
            for (int q = 0; q < 4; q++) {
                float4 a = __ldg(lep4 + ph * 4 + q);
                float4 b = __ldg(ep4 + ph * 4 + q);
                le[4 * q] = a.x; le[4 * q + 1] = a.y; le[4 * q + 2] = a.z; le[4 * q + 3] = a.w;
                ee[4 * q] = b.x; ee[4 * q + 1] = b.y; ee[4 * q + 2] = b.z; ee[4 * q + 3] = b.w;
            }
#pragma unroll
            for (int kk = 0; kk < 16; kk++) {
                int k = ph * 16 + kk;
                float a = le[kk] + ee[kk], m = le[kk] * ee[kk];
                ull a2 = pack2(a, a), m2 = pack2(m, m);
                const ulonglong2 *wA = (const ulonglong2 *)(sW1 + k * 32);
                const ulonglong2 *wB = (const ulonglong2 *)(sW2 + k * 32);
#pragma unroll
                for (int j = 0; j < 16; j++) {
                    ulonglong2 pa = wA[j];
                    ulonglong2 pb = wB[j];
                    acc[2 * j]     = ffma2(a2, pa.x, acc[2 * j]);
                    acc[2 * j + 1] = ffma2(a2, pa.y, acc[2 * j + 1]);
                    acc[2 * j]     = ffma2(m2, pb.x, acc[2 * j]);
                    acc[2 * j + 1] = ffma2(m2, pb.y, acc[2 * j + 1]);
                }
            }
        }

        float4 *o = g_E4 + (size_t)rrow * 16;
        __half2 *oh = g_Eh + (size_t)rrow * 32;
#pragma unroll
        for (int j = 0; j < 16; j++) {
            float x0, x1, x2, x3;
            unpack2(acc[2 * j], x0, x1);
            unpack2(acc[2 * j + 1], x2, x3);
            x0 = (x0 >= 0.f) ? x0 : 0.2f * x0;
            x1 = (x1 >= 0.f) ? x1 : 0.2f * x1;
            x2 = (x2 >= 0.f) ? x2 : 0.2f * x2;
            x3 = (x3 >= 0.f) ? x3 : 0.2f * x3;
            o[j] = make_float4(x0, x1, x2, x3);
            oh[2 * j]     = __floats2half2_rn(x0, x1);
            oh[2 * j + 1] = __floats2half2_rn(x2, x3);
        }
    }
}

// ================= final layer: GEMM + leaky + norm for slot rows =================
__global__ __launch_bounds__(128) void k_layer3(const float *__restrict__ w1,
                                                const float *__restrict__ b1,
                                                const float *__restrict__ w2,
                                                const float *__restrict__ b2,
                                                float *__restrict__ out) {
    __shared__ ull sW1[2048], sW2[2048], sB[32];
    const ull *w1p = (const ull *)w1;
    const ull *w2p = (const ull *)w2;
    for (int i = threadIdx.x; i < 2048; i += 128) { sW1[i] = w1p[i]; sW2[i] = w2p[i]; }
    if (threadIdx.x < 32) {
        int t = threadIdx.x;
        sB[t] = pack2(b1[2 * t] + b2[2 * t], b1[2 * t + 1] + b2[2 * t + 1]);
    }
    __syncthreads();

    int s = blockIdx.x * 128 + threadIdx.x;
    if (s >= NSLOT) return;
    int rrow = g_slot[s];

    ull acc[32];
#pragma unroll
    for (int j = 0; j < 32; j++) acc[j] = sB[j];

    const float4 *lep4 = (const float4 *)(g_LE4 + (size_t)rrow * 16);
    const float4 *ep4  = (const float4 *)(g_E4 + (size_t)rrow * 16);

#pragma unroll
    for (int ph = 0; ph < 4; ph++) {
        float le[16], ee[16];
#pragma unroll
        for (int q = 0; q < 4; q++) {
            float4 a = __ldg(lep4 + ph * 4 + q);
            float4 b = __ldg(ep4 + ph * 4 + q);
            le[4 * q] = a.x; le[4 * q + 1] = a.y; le[4 * q + 2] = a.z; le[4 * q + 3] = a.w;
            ee[4 * q] = b.x; ee[4 * q + 1] = b.y; ee[4 * q + 2] = b.z; ee[4 * q + 3] = b.w;
        }
#pragma unroll
        for (int kk = 0; kk < 16; kk++) {
            int k = ph * 16 + kk;
            float a = le[kk] + ee[kk], m = le[kk] * ee[kk];
            ull a2 = pack2(a, a), m2 = pack2(m, m);
            const ulonglong2 *wA = (const ulonglong2 *)(sW1 + k * 32);
            const ulonglong2 *wB = (const ulonglong2 *)(sW2 + k * 32);
#pragma unroll
            for (int j = 0; j < 16; j++) {
                ulonglong2 pa = wA[j];
                ulonglong2 pb = wB[j];
                acc[2 * j]     = ffma2(a2, pa.x, acc[2 * j]);
                acc[2 * j + 1] = ffma2(a2, pa.y, acc[2 * j + 1]);
                acc[2 * j]     = ffma2(m2, pb.x, acc[2 * j]);
                acc[2 * j + 1] = ffma2(m2, pb.y, acc[2 * j + 1]);
            }
        }
    }

    float ss = 0.f;
#pragma unroll
    for (int j = 0; j < 32; j++) {
        float x, y;
        unpack2(acc[j], x, y);
        x = (x >= 0.f) ? x : 0.2f * x;
        y = (y >= 0.f) ? y : 0.2f * y;
        acc[j] = pack2(x, y);
        ss += x * x + y * y;
    }
    float sc = 1.0f / fmaxf(sqrtf(ss), 1e-12f);
    float *op = out + (size_t)s * 256 + 192;
#pragma unroll
    for (int j = 0; j < 16; j++) {
        float x0, x1, x2, x3;
        unpack2(acc[2 * j], x0, x1);
        unpack2(acc[2 * j + 1], x2, x3);
        ((float4 *)op)[j] = make_float4(x0 * sc, x1 * sc, x2 * sc, x3 * sc);
    }
}

// =================================================================================
extern "C" void kernel_launch(void* const* d_in, const int* in_sizes, int n_in,
                              void* d_out, int out_size) {
    const float *user_emb, *item_emb, *user_feat, *lin1_w, *lin1_b, *lin2_w, *lin2_b;
    const float *w1, *b1, *w2, *b2, *lap_val, *mlp_ratio;
    const int *lap_row, *lap_col, *user_idx, *pos_idx, *neg_idx;

    if (in_sizes[2] == 4096) {
        user_emb  = (const float *)d_in[0];
        item_emb  = (const float *)d_in[1];
        user_feat = (const float *)d_in[2];
        lin1_w    = (const float *)d_in[3];
        lin1_b    = (const float *)d_in[4];
        lin2_w    = (const float *)d_in[5];
        lin2_b    = (const float *)d_in[6];
        w1        = (const float *)d_in[7];
        b1        = (const float *)d_in[8];
        w2        = (const float *)d_in[9];
        b2        = (const float *)d_in[10];
        lap_val   = (const float *)d_in[11];
        mlp_ratio = (const float *)d_in[12];
        lap_row   = (const int *)d_in[13];
        lap_col   = (const int *)d_in[14];
        user_idx  = (const int *)d_in[15];
        pos_idx   = (const int *)d_in[16];
        neg_idx   = (const int *)d_in[17];
    } else {
        user_emb  = (const float *)d_in[0];
        item_emb  = (const float *)d_in[1];
        lin1_w    = (const float *)d_in[2];
        lin1_b    = (const float *)d_in[3];
        lin2_w    = (const float *)d_in[4];
        lin2_b    = (const float *)d_in[5];
        w1        = (const float *)d_in[6];
        b1        = (const float *)d_in[7];
        w2        = (const float *)d_in[8];
        b2        = (const float *)d_in[9];
        lap_row   = (const int *)d_in[10];
        lap_col   = (const int *)d_in[11];
        lap_val   = (const float *)d_in[12];
        user_idx  = (const int *)d_in[13];
        user_feat = (const float *)d_in[14];
        pos_idx   = (const int *)d_in[15];
        neg_idx   = (const int *)d_in[16];
        mlp_ratio = (const float *)d_in[17];
    }

    float *out = (float *)d_out;
    const float2 *item2 = (const float2 *)item_emb;

    const int T = 256;
    const int gGath  = (NSLOT * 32) / T;            // 384
    const int gSpmmF = (NNODE * 32 + T - 1) / T;    // 18750
    const int gSp2   = SP2_WARPS / 8;               // 4736
    const int gSp3   = (NSLOT * 32) / T;            // 384
    const int gGemm  = (NNODE + 127) / 128;         // 1172
    const int gL3    = (NSLOT + 127) / 128;         // 24

    // 0: user E0 copy(+fp16) + item fp16 + zero aux
    k_init<<<INIT_BLKS, T>>>((const float4 *)user_emb, (const float4 *)item_emb);
    // 1: fused MLP+scatter-update(+fp16) + slots/flags
    k_prep<<<16, T>>>(user_idx, user_emb, mlp_ratio, pos_idx, neg_idx,
                      lin1_w, lin1_b, lin2_w, lin2_b, user_feat);
    // 2: persistent CSR build (hist+flag2+gather0 -> scan+list2 -> scatter)
    k_csr<<<CSR_BLKS, T>>>(lap_row, lap_col, lap_val, out, item2);
    // 3: layer-1 SpMM (full, fp16 gather)   <-- profiled slot
    k_spmm<0><<<gSpmmF, T>>>(gSpmmF, nullptr, 0);
    // 4: layer-1 GEMM (full) + fp16 epilogue
    k_gemm<0><<<gGemm, 128>>>(w1, b1, w2, b2, item2);
    // 5: layer-2 SpMM (list2, strided) || gather E1 -> out[:,64:128]
    k_spmm<1><<<gSp2 + gGath, T>>>(gSp2, out, 64);
    // 6: layer-2 GEMM (list2, strided) + fp16 epilogue
    k_gemm<1><<<400, 128>>>(w1 + 4096, b1 + 64, w2 + 4096, b2 + 64, item2);
    // 7: layer-3 SpMM (slots) || gather E2 -> out[:,128:192]
    k_spmm<2><<<gSp3 + gGath, T>>>(gSp3, out, 128);
    // 8: layer-3 GEMM + leaky + norm -> out[:,192:256]
    k_layer3<<<gL3, 128>>>(w1 + 2 * 4096, b1 + 2 * 64, w2 + 2 * 4096, b2 + 2 * 64, out);
}

// round 16
// speedup vs baseline: 2.4060x; 1.1972x over previous
#include <cuda_runtime.h>
#include <cuda_bf16.h>
#include <cuda_fp16.h>
#include <math.h>

#define NUSER 50000
#define NITEM 100000
#define NNODE 150000
#define DD    64
#define NNZV  2400000
#define BB    1024
#define NSLOT 3072
#define SCAN_TILE 1024
#define NTILES ((NNODE + SCAN_TILE - 1) / SCAN_TILE)   // 147
#define SP2_WARPS 37888                                 // 4736 blocks * 8 warps

typedef unsigned long long ull;

// ---------------- device scratch --------------------------------------------------
__device__ float4  g_E4[NNODE * 16];     // fp32 node embeddings, in-place per layer
__device__ __half2 g_Eh[NNODE * 32];     // fp16 mirror of E (19.2MB)
__device__ __half2 g_LEh[NNODE * 32];    // fp16 SpMM result LE (19.2MB)
__device__ int     g_slot[NSLOT];
__device__ unsigned char g_flag3[NNODE];
__device__ unsigned char g_flag2[NNODE];
__device__ int  g_list2[NNODE];
__device__ int  g_n2;
__device__ int  g_cnt[NNODE];
__device__ int  g_rp[NNODE + 1];
__device__ int  g_pos[NNODE];
__device__ int  g_tflag[NTILES];
__device__ int2 g_cv[NNZV];              // (col, val bits) row-sorted (19.2MB)

// ---------------- f32x2 packed-math helpers ---------------------------------------
__device__ __forceinline__ ull pack2(float x, float y) {
    ull r; asm("mov.b64 %0, {%1, %2};" : "=l"(r) : "f"(x), "f"(y)); return r;
}
__device__ __forceinline__ void unpack2(ull v, float &x, float &y) {
    asm("mov.b64 {%0, %1}, %2;" : "=f"(x), "=f"(y) : "l"(v));
}
__device__ __forceinline__ ull ffma2(ull a, ull b, ull c) {
    ull d; asm("fma.rn.f32x2 %0, %1, %2, %3;" : "=l"(d) : "l"(a), "l"(b), "l"(c)); return d;
}

// E0 fp32 row: users in g_E4, items straight from input
__device__ __forceinline__ const float2 *e0row(int c, const float2 *__restrict__ item2) {
    return (c < NUSER) ? ((const float2 *)g_E4) + (size_t)c * 32
                       : item2 + (size_t)(c - NUSER) * 32;
}

// ================= launch 0: user E copy + fp16 ===================================
#define COPYU_BLKS 3125            // NUSER*16/256
__global__ void k_init_a(const float4 *__restrict__ ue) {
    int i = blockIdx.x * 256 + threadIdx.x;       // < NUSER*16 exactly
    float4 v = ue[i];
    g_E4[i] = v;
    g_Eh[2 * i]     = __floats2half2_rn(v.x, v.y);
    g_Eh[2 * i + 1] = __floats2half2_rn(v.z, v.w);
}

// ================= launch 1: item fp16 + zero aux =================================
#define ITEM_BLKS 6250             // NITEM*16/256
#define ZERO_BLKS 586
__global__ void k_init_b(const float4 *__restrict__ ie) {
    int bid = blockIdx.x, tid = threadIdx.x;
    if (bid < ITEM_BLKS) {
        int i = bid * 256 + tid;                  // < NITEM*16 exactly
        float4 v = ie[i];
        int o = NUSER * 16 + i;
        g_Eh[2 * o]     = __floats2half2_rn(v.x, v.y);
        g_Eh[2 * o + 1] = __floats2half2_rn(v.z, v.w);
        return;
    }
    int i = (bid - ITEM_BLKS) * 256 + tid;
    if (i < NNODE) { g_cnt[i] = 0; g_flag3[i] = 0; g_flag2[i] = 0; }
    if (i < NTILES) g_tflag[i] = 0;
    if (i == 0) g_n2 = 0;
}

// ================= launch 2: MLP+update (last wins) + slots/flags =================
__global__ void k_prep(const int *__restrict__ uidx, const float *__restrict__ uemb,
                       const float *__restrict__ ratio,
                       const int *__restrict__ pi, const int *__restrict__ ni,
                       const float *__restrict__ l1w, const float *__restrict__ l1b,
                       const float *__restrict__ l2w, const float *__restrict__ l2b,
                       const float *__restrict__ feat) {
    int bid = blockIdx.x, tid = threadIdx.x;
    if (bid < 4) {
        int b = bid * 256 + tid;
        if (b >= BB) return;
        int u = uidx[b];
        for (int b2 = b + 1; b2 < BB; b2++)
            if (uidx[b2] == u) return;            // later duplicate wins
        float f0 = feat[b * 4 + 0], f1 = feat[b * 4 + 1];
        float f2 = feat[b * 4 + 2], f3 = feat[b * 4 + 3];
        float h[32];
#pragma unroll
        for (int j = 0; j < 32; j++)
            h[j] = l1b[j] + f0 * l1w[j] + f1 * l1w[32 + j] + f2 * l1w[64 + j] + f3 * l1w[96 + j];
        float r = *ratio;
        float e[64];
#pragma unroll 4
        for (int o = 0; o < 64; o++) {
            float a = l2b[o];
#pragma unroll
            for (int j = 0; j < 32; j++) a += h[j] * l2w[j * 64 + o];
            e[o] = uemb[u * 64 + o] * (1.0f - r) + a * r;
        }
        float4 *er = g_E4 + (size_t)u * 16;
        __half2 *eh = g_Eh + (size_t)u * 32;
#pragma unroll
        for (int j = 0; j < 16; j++) {
            er[j] = make_float4(e[4 * j], e[4 * j + 1], e[4 * j + 2], e[4 * j + 3]);
            eh[2 * j]     = __floats2half2_rn(e[4 * j], e[4 * j + 1]);
            eh[2 * j + 1] = __floats2half2_rn(e[4 * j + 2], e[4 * j + 3]);
        }
        return;
    }
    int s = (bid - 4) * 256 + tid;
    if (s >= NSLOT) return;
    int node;
    if (s < 1024)       node = uidx[s];
    else if (s < 2048)  node = NUSER + pi[s - 1024];
    else                node = NUSER + ni[s - 2048];
    g_slot[s] = node;
    g_flag3[node] = 1;
    g_flag2[node] = 1;
}

// ---------------- gather body (fp32 E, normalized) --------------------------------
__device__ __forceinline__ void gather_body(int t, float *__restrict__ out, int col_off) {
    int slot = t >> 5, lane = t & 31;
    if (slot >= NSLOT) return;
    int node = g_slot[slot];
    float2 v = ((const float2 *)g_E4)[(size_t)node * 32 + lane];
    float s = v.x * v.x + v.y * v.y;
#pragma unroll
    for (int o = 16; o > 0; o >>= 1) s += __shfl_xor_sync(0xffffffffu, s, o);
    float sc = 1.0f / fmaxf(sqrtf(s), 1e-12f);
    v.x *= sc; v.y *= sc;
    ((float2 *)(out + (size_t)slot * 256 + col_off))[lane] = v;
}

// ================= launch 3: histogram + flag2 propagate + gather0 ================
#define NNZ_BLKS 9375
__global__ void k_nnzpass(const int *__restrict__ row, const int *__restrict__ col,
                          float *__restrict__ out, const float2 *__restrict__ item2) {
    int bid = blockIdx.x, tid = threadIdx.x;
    if (bid < NNZ_BLKS) {
        int i = bid * 256 + tid;
        if (i >= NNZV) return;
        int r = __ldg(row + i);
        atomicAdd(&g_cnt[r], 1);
        if (g_flag3[r]) g_flag2[__ldg(col + i)] = 1;
        return;
    }
    // gather E0 slots -> out[:,0:64] (un-normalized)
    int t = (bid - NNZ_BLKS) * 256 + tid;
    int slot = t >> 5, lane = t & 31;
    if (slot >= NSLOT) return;
    int node = g_slot[slot];
    float2 v = __ldg(e0row(node, item2) + lane);
    ((float2 *)(out + (size_t)slot * 256))[lane] = v;
}

// ================= launch 4: single-pass scan (decoupled lookback) ================
__global__ void k_scan() {
    __shared__ int wsum[8], rs[8], sS;
    int tid = threadIdx.x, lane = tid & 31, wid = tid >> 5, blk = blockIdx.x;
    int idx = blk * SCAN_TILE + tid * 4;
    int v0 = (idx + 0 < NNODE) ? g_cnt[idx + 0] : 0;
    int v1 = (idx + 1 < NNODE) ? g_cnt[idx + 1] : 0;
    int v2 = (idx + 2 < NNODE) ? g_cnt[idx + 2] : 0;
    int v3 = (idx + 3 < NNODE) ? g_cnt[idx + 3] : 0;
    int s = v0 + v1 + v2 + v3;
    int x = s;
#pragma unroll
    for (int o = 1; o < 32; o <<= 1) {
        int y = __shfl_up_sync(0xffffffffu, x, o);
        if (lane >= o) x += y;
    }
    if (lane == 31) wsum[wid] = x;
    __syncthreads();
    if (wid == 0) {
        int y = (lane < 8) ? wsum[lane] : 0;
#pragma unroll
        for (int o = 1; o < 8; o <<= 1) {
            int z = __shfl_up_sync(0xffffffffu, y, o);
            if (lane >= o) y += z;
        }
        if (lane < 8) wsum[lane] = y;
    }
    __syncthreads();
    int run = x - s + (wid > 0 ? wsum[wid - 1] : 0);
    if (tid == 0) atomicExch(&g_tflag[blk], wsum[7] + 1);
    int v = 0;
    if (tid < blk) {
        int t;
        while ((t = atomicAdd(&g_tflag[tid], 0)) == 0) {}
        v = t - 1;
    }
#pragma unroll
    for (int o = 16; o > 0; o >>= 1) v += __shfl_xor_sync(0xffffffffu, v, o);
    if (lane == 0) rs[wid] = v;
    __syncthreads();
    if (tid == 0) {
        int S = 0;
#pragma unroll
        for (int i = 0; i < 8; i++) S += rs[i];
        sS = S;
    }
    __syncthreads();
    int S = sS;
    int r0 = run + S, r1 = r0 + v0, r2 = r1 + v1, r3 = r2 + v2;
    if (idx + 0 < NNODE) { g_rp[idx + 0] = r0; g_pos[idx + 0] = r0;
        if (g_flag2[idx + 0]) g_list2[atomicAdd(&g_n2, 1)] = idx + 0; }
    if (idx + 1 < NNODE) { g_rp[idx + 1] = r1; g_pos[idx + 1] = r1;
        if (g_flag2[idx + 1]) g_list2[atomicAdd(&g_n2, 1)] = idx + 1; }
    if (idx + 2 < NNODE) { g_rp[idx + 2] = r2; g_pos[idx + 2] = r2;
        if (g_flag2[idx + 2]) g_list2[atomicAdd(&g_n2, 1)] = idx + 2; }
    if (idx + 3 < NNODE) { g_rp[idx + 3] = r3; g_pos[idx + 3] = r3;
        if (g_flag2[idx + 3]) g_list2[atomicAdd(&g_n2, 1)] = idx + 3; }
    if (blk == 0 && tid == 0) g_rp[NNODE] = NNZV;
}

// ================= launch 5: scatter (col,val) row-sorted =========================
__global__ void k_scatter(const int *__restrict__ row, const int *__restrict__ col,
                          const float *__restrict__ val) {
    int i = blockIdx.x * blockDim.x + threadIdx.x;
    if (i >= NNZV) return;
    int p = atomicAdd(&g_pos[row[i]], 1);
    g_cv[p] = make_int2(col[i], __float_as_int(val[i]));
}

// ================= CSR SpMM row body: fp16 gather, fp32 acc, fp16 LE out ==========
__device__ __forceinline__ void spmm_row(int r, int lane) {
    int j = __ldg(&g_rp[r]), end = __ldg(&g_rp[r + 1]);
    float ax = 0.f, ay = 0.f;
#define LDE(c) __half22float2(__ldg(g_Eh + (size_t)(c) * 32 + lane))
    if ((j & 1) && j < end) {
        int2 c = __ldg(g_cv + j);
        float2 e = LDE(c.x);
        float v = __int_as_float(c.y);
        ax += v * e.x; ay += v * e.y;
        j++;
    }
    for (; j + 8 <= end; j += 8) {
        int4 q0 = __ldg((const int4 *)(g_cv + j));
        int4 q1 = __ldg((const int4 *)(g_cv + j + 2));
        int4 q2 = __ldg((const int4 *)(g_cv + j + 4));
        int4 q3 = __ldg((const int4 *)(g_cv + j + 6));
        float2 e0 = LDE(q0.x), e1 = LDE(q0.z);
        float2 e2 = LDE(q1.x), e3 = LDE(q1.z);
        float2 e4 = LDE(q2.x), e5 = LDE(q2.z);
        float2 e6 = LDE(q3.x), e7 = LDE(q3.z);
        ax += __int_as_float(q0.y) * e0.x; ay += __int_as_float(q0.y) * e0.y;
        ax += __int_as_float(q0.w) * e1.x; ay += __int_as_float(q0.w) * e1.y;
        ax += __int_as_float(q1.y) * e2.x; ay += __int_as_float(q1.y) * e2.y;
        ax += __int_as_float(q1.w) * e3.x; ay += __int_as_float(q1.w) * e3.y;
        ax += __int_as_float(q2.y) * e4.x; ay += __int_as_float(q2.y) * e4.y;
        ax += __int_as_float(q2.w) * e5.x; ay += __int_as_float(q2.w) * e5.y;
        ax += __int_as_float(q3.y) * e6.x; ay += __int_as_float(q3.y) * e6.y;
        ax += __int_as_float(q3.w) * e7.x; ay += __int_as_float(q3.w) * e7.y;
    }
    for (; j < end; j++) {
        int2 c = __ldg(g_cv + j);
        float2 e = LDE(c.x);
        float v = __int_as_float(c.y);
        ax += v * e.x; ay += v * e.y;
    }
#undef LDE
    g_LEh[(size_t)r * 32 + lane] = __floats2half2_rn(ax, ay);
}

// MODE 0 = all rows (flat), 1 = list2 rows (grid-strided), 2 = slot rows (flat)
template <int MODE>
__global__ void k_spmm(int spmm_blks, float *__restrict__ out, int col_off) {
    int bid = blockIdx.x;
    if (MODE != 0 && bid >= spmm_blks) {
        gather_body((bid - spmm_blks) * 256 + threadIdx.x, out, col_off);
        return;
    }
    int lane = threadIdx.x & 31;
    int w = (bid * blockDim.x + threadIdx.x) >> 5;
    if (MODE == 0) {
        if (w < NNODE) spmm_row(w, lane);
    } else if (MODE == 1) {
        int n2 = g_n2;
        for (; w < n2; w += SP2_WARPS) spmm_row(g_list2[w], lane);
    } else {
        if (w < NSLOT) spmm_row(g_slot[w], lane);
    }
}

// ================= staged GEMM + leaky_relu, E in place, fp16 mirror ==============
// MODE 0 = all rows (layer 1), 1 = list2 rows (layer 2). Inputs: g_LEh + g_Eh (fp16).
// smem: sW1[2048] ull | sW2[2048] ull | sB[32] ull | sLE[128*33] h2 | sE[128*33] h2
#define GSMEM_BYTES (4128 * 8 + 2 * 128 * 33 * 4)    // 33024 + 33792 = 66816
template <int MODE>
__global__ __launch_bounds__(128) void k_gemm(const float *__restrict__ w1,
                                              const float *__restrict__ b1,
                                              const float *__restrict__ w2,
                                              const float *__restrict__ b2) {
    extern __shared__ ull smem_u[];
    ull *sW1 = smem_u;
    ull *sW2 = smem_u + 2048;
    ull *sB  = smem_u + 4096;
    __half2 *sLE = (__half2 *)(smem_u + 4128);
    __half2 *sE  = sLE + 128 * 33;

    for (int i = threadIdx.x; i < 2048; i += 128) {
        sW1[i] = ((const ull *)w1)[i];
        sW2[i] = ((const ull *)w2)[i];
    }
    if (threadIdx.x < 32) {
        int t = threadIdx.x;
        sB[t] = pack2(b1[2 * t] + b2[2 * t], b1[2 * t + 1] + b2[2 * t + 1]);
    }
    __syncthreads();

    int wid = threadIdx.x >> 5, lane = threadIdx.x & 31;
    int nrows = (MODE == 0) ? NNODE : g_n2;

    for (int base = blockIdx.x * 128; base < nrows; base += gridDim.x * 128) {
        // ---- stage: warp cooperatively loads its 32 rows (coalesced 128B/row) ----
#pragma unroll 4
        for (int rr = 0; rr < 32; rr++) {
            int g = base + wid * 32 + rr;
            if (g < nrows) {
                int r = (MODE == 0) ? g : g_list2[g];
                int l = wid * 32 + rr;
                sLE[l * 33 + lane] = __ldg(g_LEh + (size_t)r * 32 + lane);
                sE [l * 33 + lane] = __ldg(g_Eh  + (size_t)r * 32 + lane);
            }
        }
        __syncwarp();

        // ---- compute: thread-per-row from smem ----
        int gg = base + threadIdx.x;
        if (gg < nrows) {
            int r = (MODE == 0) ? gg : g_list2[gg];
            const __half2 *myLE = sLE + threadIdx.x * 33;
            const __half2 *myE  = sE  + threadIdx.x * 33;

            ull acc[32];
#pragma unroll
            for (int j = 0; j < 32; j++) acc[j] = sB[j];

#pragma unroll 8
            for (int kk = 0; kk < 32; kk++) {
                float2 le = __half22float2(myLE[kk]);
                float2 ee = __half22float2(myE[kk]);
#pragma unroll
                for (int h = 0; h < 2; h++) {
                    int k = 2 * kk + h;
                    float lev = h ? le.y : le.x;
                    float eev = h ? ee.y : ee.x;
                    float a = lev + eev, m = lev * eev;
                    ull a2 = pack2(a, a), m2 = pack2(m, m);
                    const ulonglong2 *wA = (const ulonglong2 *)(sW1 + k * 32);
                    const ulonglong2 *wB = (const ulonglong2 *)(sW2 + k * 32);
#pragma unroll
                    for (int j = 0; j < 16; j++) {
                        ulonglong2 pa = wA[j];
                        ulonglong2 pb = wB[j];
                        acc[2 * j]     = ffma2(a2, pa.x, acc[2 * j]);
                        acc[2 * j + 1] = ffma2(a2, pa.y, acc[2 * j + 1]);
                        acc[2 * j]     = ffma2(m2, pb.x, acc[2 * j]);
                        acc[2 * j + 1] = ffma2(m2, pb.y, acc[2 * j + 1]);
                    }
                }
            }

            float4 *o = g_E4 + (size_t)r * 16;
            __half2 *oh = g_Eh + (size_t)r * 32;
#pragma unroll
            for (int j = 0; j < 16; j++) {
                float x0, x1, x2, x3;
                unpack2(acc[2 * j], x0, x1);
                unpack2(acc[2 * j + 1], x2, x3);
                x0 = (x0 >= 0.f) ? x0 : 0.2f * x0;
                x1 = (x1 >= 0.f) ? x1 : 0.2f * x1;
                x2 = (x2 >= 0.f) ? x2 : 0.2f * x2;
                x3 = (x3 >= 0.f) ? x3 : 0.2f * x3;
                o[j] = make_float4(x0, x1, x2, x3);
                oh[2 * j]     = __floats2half2_rn(x0, x1);
                oh[2 * j + 1] = __floats2half2_rn(x2, x3);
            }
        }
        __syncwarp();   // warp-local staging buffer reuse
    }
}

// ================= final layer: GEMM + leaky + norm for slot rows =================
__global__ __launch_bounds__(128) void k_layer3(const float *__restrict__ w1,
                                                const float *__restrict__ b1,
                                                const float *__restrict__ w2,
                                                const float *__restrict__ b2,
                                                float *__restrict__ out) {
    __shared__ ull sW1[2048], sW2[2048], sB[32];
    for (int i = threadIdx.x; i < 2048; i += 128) {
        sW1[i] = ((const ull *)w1)[i];
        sW2[i] = ((const ull *)w2)[i];
    }
    if (threadIdx.x < 32) {
        int t = threadIdx.x;
        sB[t] = pack2(b1[2 * t] + b2[2 * t], b1[2 * t + 1] + b2[2 * t + 1]);
    }
    __syncthreads();

    int s = blockIdx.x * 128 + threadIdx.x;
    if (s >= NSLOT) return;
    int rrow = g_slot[s];

    ull acc[32];
#pragma unroll
    for (int j = 0; j < 32; j++) acc[j] = sB[j];

    const __half2 *lep = g_LEh + (size_t)rrow * 32;
    const float2  *ep  = ((const float2 *)g_E4) + (size_t)rrow * 32;

#pragma unroll 8
    for (int kk = 0; kk < 32; kk++) {
        float2 le = __half22float2(__ldg(lep + kk));
        float2 ee = __ldg(ep + kk);
#pragma unroll
        for (int h = 0; h < 2; h++) {
            int k = 2 * kk + h;
            float lev = h ? le.y : le.x;
            float eev = h ? ee.y : ee.x;
            float a = lev + eev, m = lev * eev;
            ull a2 = pack2(a, a), m2 = pack2(m, m);
            const ulonglong2 *wA = (const ulonglong2 *)(sW1 + k * 32);
            const ulonglong2 *wB = (const ulonglong2 *)(sW2 + k * 32);
#pragma unroll
            for (int j = 0; j < 16; j++) {
                ulonglong2 pa = wA[j];
                ulonglong2 pb = wB[j];
                acc[2 * j]     = ffma2(a2, pa.x, acc[2 * j]);
                acc[2 * j + 1] = ffma2(a2, pa.y, acc[2 * j + 1]);
                acc[2 * j]     = ffma2(m2, pb.x, acc[2 * j]);
                acc[2 * j + 1] = ffma2(m2, pb.y, acc[2 * j + 1]);
            }
        }
    }

    float ss = 0.f;
#pragma unroll
    for (int j = 0; j < 32; j++) {
        float x, y;
        unpack2(acc[j], x, y);
        x = (x >= 0.f) ? x : 0.2f * x;
        y = (y >= 0.f) ? y : 0.2f * y;
        acc[j] = pack2(x, y);
        ss += x * x + y * y;
    }
    float sc = 1.0f / fmaxf(sqrtf(ss), 1e-12f);
    float *op = out + (size_t)s * 256 + 192;
#pragma unroll
    for (int j = 0; j < 16; j++) {
        float x0, x1, x2, x3;
        unpack2(acc[2 * j], x0, x1);
        unpack2(acc[2 * j + 1], x2, x3);
        ((float4 *)op)[j] = make_float4(x0 * sc, x1 * sc, x2 * sc, x3 * sc);
    }
}

// =================================================================================
extern "C" void kernel_launch(void* const* d_in, const int* in_sizes, int n_in,
                              void* d_out, int out_size) {
    const float *user_emb, *item_emb, *user_feat, *lin1_w, *lin1_b, *lin2_w, *lin2_b;
    const float *w1, *b1, *w2, *b2, *lap_val, *mlp_ratio;
    const int *lap_row, *lap_col, *user_idx, *pos_idx, *neg_idx;

    if (in_sizes[2] == 4096) {
        user_emb  = (const float *)d_in[0];
        item_emb  = (const float *)d_in[1];
        user_feat = (const float *)d_in[2];
        lin1_w    = (const float *)d_in[3];
        lin1_b    = (const float *)d_in[4];
        lin2_w    = (const float *)d_in[5];
        lin2_b    = (const float *)d_in[6];
        w1        = (const float *)d_in[7];
        b1        = (const float *)d_in[8];
        w2        = (const float *)d_in[9];
        b2        = (const float *)d_in[10];
        lap_val   = (const float *)d_in[11];
        mlp_ratio = (const float *)d_in[12];
        lap_row   = (const int *)d_in[13];
        lap_col   = (const int *)d_in[14];
        user_idx  = (const int *)d_in[15];
        pos_idx   = (const int *)d_in[16];
        neg_idx   = (const int *)d_in[17];
    } else {
        user_emb  = (const float *)d_in[0];
        item_emb  = (const float *)d_in[1];
        lin1_w    = (const float *)d_in[2];
        lin1_b    = (const float *)d_in[3];
        lin2_w    = (const float *)d_in[4];
        lin2_b    = (const float *)d_in[5];
        w1        = (const float *)d_in[6];
        b1        = (const float *)d_in[7];
        w2        = (const float *)d_in[8];
        b2        = (const float *)d_in[9];
        lap_row   = (const int *)d_in[10];
        lap_col   = (const int *)d_in[11];
        lap_val   = (const float *)d_in[12];
        user_idx  = (const int *)d_in[13];
        user_feat = (const float *)d_in[14];
        pos_idx   = (const int *)d_in[15];
        neg_idx   = (const int *)d_in[16];
        mlp_ratio = (const float *)d_in[17];
    }

    float *out = (float *)d_out;
    const float2 *item2 = (const float2 *)item_emb;

    cudaFuncSetAttribute(k_gemm<0>, cudaFuncAttributeMaxDynamicSharedMemorySize, GSMEM_BYTES);
    cudaFuncSetAttribute(k_gemm<1>, cudaFuncAttributeMaxDynamicSharedMemorySize, GSMEM_BYTES);

    const int T = 256;
    const int gGath  = (NSLOT * 32) / T;            // 384
    const int gNnz   = (NNZV + T - 1) / T;          // 9375
    const int gSpmmF = (NNODE * 32 + T - 1) / T;    // 18750
    const int gSp2   = SP2_WARPS / 8;               // 4736
    const int gSp3   = (NSLOT * 32) / T;            // 384
    const int gGemm  = (NNODE + 127) / 128;         // 1172
    const int gL3    = (NSLOT + 127) / 128;         // 24

    // 0-1: init (user copy+fp16; item fp16 + zero aux)
    k_init_a<<<COPYU_BLKS, T>>>((const float4 *)user_emb);
    k_init_b<<<ITEM_BLKS + ZERO_BLKS, T>>>((const float4 *)item_emb);
    // 2: fused MLP+scatter-update(+fp16) + slots/flags
    k_prep<<<16, T>>>(user_idx, user_emb, mlp_ratio, pos_idx, neg_idx,
                      lin1_w, lin1_b, lin2_w, lin2_b, user_feat);
    // 3: histogram + flag2 + gather0   <-- profiled slot
    k_nnzpass<<<NNZ_BLKS + gGath, T>>>(lap_row, lap_col, out, item2);
    // 4: single-pass scan + list2
    k_scan<<<NTILES, T>>>();
    // 5: CSR scatter
    k_scatter<<<gNnz, T>>>(lap_row, lap_col, lap_val);
    // 6: layer-1 SpMM (full) -> g_LEh
    k_spmm<0><<<gSpmmF, T>>>(gSpmmF, nullptr, 0);
    // 7: layer-1 GEMM (staged)
    k_gemm<0><<<gGemm, 128, GSMEM_BYTES>>>(w1, b1, w2, b2);
    // 8: layer-2 SpMM (list2, strided) || gather E1 -> out[:,64:128]
    k_spmm<1><<<gSp2 + gGath, T>>>(gSp2, out, 64);
    // 9: layer-2 GEMM (staged, strided)
    k_gemm<1><<<400, 128, GSMEM_BYTES>>>(w1 + 4096, b1 + 64, w2 + 4096, b2 + 64);
    // 10: layer-3 SpMM (slots) || gather E2 -> out[:,128:192]
    k_spmm<2><<<gSp3 + gGath, T>>>(gSp3, out, 128);
    // 11: layer-3 GEMM + leaky + norm -> out[:,192:256]
    k_layer3<<<gL3, 128>>>(w1 + 2 * 4096, b1 + 2 * 64, w2 + 2 * 4096, b2 + 2 * 64, out);
}